// round 12
// baseline (speedup 1.0000x reference)
#include <cuda_runtime.h>

#define FULL 0xffffffffu

// ---------------- persistent scratch (self-resetting across replays) --------
__device__ float    g_F[8 * 81];        // grid evaluations of <Z_j>, [j][n]
__device__ unsigned g_ctr  = 0;         // producers done
__device__ unsigned g_done = 0;         // blocks done
__device__ float    g_partial[32] = {}; // per-batch dense accumulators

// ---------------- warp statevector simulation (producer phase) --------------
// flat index i = lane*8 + m. qubit q (0..4) -> lane bit (4-q); qubit q (5..7)
// -> m bit (7-q).
struct St { float2 a[8]; };

__device__ __forceinline__ float2 shxor(float2 v, int m) {
    float2 r;
    r.x = __shfl_xor_sync(FULL, v.x, m);
    r.y = __shfl_xor_sync(FULL, v.y, m);
    return r;
}

// RY (data encoding on qubits 0-3: lane-bit qubits)
template<int Q>
__device__ __forceinline__ void gateRY(St& st, float c, float s, int lane) {
    constexpr int lm = 1 << (4 - Q);
    float sg = (lane & lm) ? s : -s;
#pragma unroll
    for (int m = 0; m < 8; ++m) {
        float2 o = shxor(st.a[m], lm);
        float2 a = st.a[m];
        st.a[m] = make_float2(c * a.x + sg * o.x, c * a.y + sg * o.y);
    }
}

// RX = [[c,-is],[-is,c]]
template<int Q>
__device__ __forceinline__ void gateRX(St& st, float c, float s, int lane) {
    if constexpr (Q >= 5) {
        constexpr int bit = 1 << (7 - Q);
#pragma unroll
        for (int m = 0; m < 8; ++m) {
            if ((m & bit) == 0) {
                float2 a = st.a[m], b = st.a[m | bit];
                st.a[m]       = make_float2(c * a.x + s * b.y, c * a.y - s * b.x);
                st.a[m | bit] = make_float2(c * b.x + s * a.y, c * b.y - s * a.x);
            }
        }
    } else {
        constexpr int lm = 1 << (4 - Q);
#pragma unroll
        for (int m = 0; m < 8; ++m) {
            float2 o = shxor(st.a[m], lm);
            float2 a = st.a[m];
            st.a[m] = make_float2(c * a.x + s * o.y, c * a.y - s * o.x);
        }
    }
}

// RZ = diag(e^{-it/2}, e^{+it/2})
template<int Q>
__device__ __forceinline__ void gateRZ(St& st, float c, float s, int lane) {
    if constexpr (Q >= 5) {
        constexpr int bit = 1 << (7 - Q);
#pragma unroll
        for (int m = 0; m < 8; ++m) {
            float f = (m & bit) ? s : -s;
            float2 a = st.a[m];
            st.a[m] = make_float2(c * a.x - f * a.y, c * a.y + f * a.x);
        }
    } else {
        constexpr int lm = 1 << (4 - Q);
        float f = (lane & lm) ? s : -s;
#pragma unroll
        for (int m = 0; m < 8; ++m) {
            float2 a = st.a[m];
            st.a[m] = make_float2(c * a.x - f * a.y, c * a.y + f * a.x);
        }
    }
}

// Fused CNOT·RY·CNOT (round-10 derivation)
template<int J>
__device__ __forceinline__ void fusedW(St& st, float c, float s, int lane) {
    if constexpr (J <= 3) {
        constexpr int cm = 1 << (4 - J);
        constexpr int tm = 1 << (3 - J);
        float sg = (lane & cm) ? s : -s;
#pragma unroll
        for (int m = 0; m < 8; ++m) {
            float2 o = shxor(st.a[m], cm | tm);
            float2 a = st.a[m];
            st.a[m] = make_float2(c * a.x + sg * o.x, c * a.y + sg * o.y);
        }
    } else if constexpr (J == 4) {
        float sg = (lane & 1) ? s : -s;
        float2 o[8];
#pragma unroll
        for (int m = 0; m < 8; ++m) o[m] = shxor(st.a[m ^ 4], 1);
#pragma unroll
        for (int m = 0; m < 8; ++m) {
            float2 a = st.a[m];
            st.a[m] = make_float2(c * a.x + sg * o[m].x, c * a.y + sg * o[m].y);
        }
    } else if constexpr (J == 5 || J == 6) {
        constexpr int cmask = (J == 5) ? 4 : 2;
        constexpr int xmask = (J == 5) ? 6 : 3;
        float2 old[8];
#pragma unroll
        for (int m = 0; m < 8; ++m) old[m] = st.a[m];
#pragma unroll
        for (int m = 0; m < 8; ++m) {
            float sg = (m & cmask) ? s : -s;
            st.a[m] = make_float2(c * old[m].x + sg * old[m ^ xmask].x,
                                  c * old[m].y + sg * old[m ^ xmask].y);
        }
    } else {
        int bc = (lane >> 4) & 1;
        float2 old[8];
#pragma unroll
        for (int m = 0; m < 8; ++m) old[m] = st.a[m];
#pragma unroll
        for (int m = 0; m < 8; ++m) {
            float sg = ((bc ^ (m & 1)) != 0) ? s : -s;
            st.a[m] = make_float2(c * old[m].x + sg * old[m ^ 1].x,
                                  c * old[m].y + sg * old[m ^ 1].y);
        }
    }
}

template<int J>
__device__ __forceinline__ void ansatzStep(St& st, const float* cw, const float* sw, int lane) {
    float c = cw[J], s = sw[J];
    gateRX<J>(st, c, s, lane);
    fusedW<J>(st, c, s, lane);
    gateRZ<J>(st, c, s, lane);
}

__device__ __forceinline__ void ansatz(St& st, const float* cw, const float* sw, int lane) {
    ansatzStep<0>(st, cw, sw, lane);
    ansatzStep<1>(st, cw, sw, lane);
    ansatzStep<2>(st, cw, sw, lane);
    ansatzStep<3>(st, cw, sw, lane);
    ansatzStep<4>(st, cw, sw, lane);
    ansatzStep<5>(st, cw, sw, lane);
    ansatzStep<6>(st, cw, sw, lane);
    ansatzStep<7>(st, cw, sw, lane);
}

// ---------------- mega kernel: one launch ------------------------------------
// 256 blocks x 256 threads. bid -> (batch = bid>>3, chunk = bid&7).
// Blocks 0..80: warp 0 produces g_F[.,bid] (all producers are in wave 1 even
// at 1 block/SM, so the flag-sync cannot deadlock). launch_bounds(256,1)
// lets ptxas allocate enough registers for the spill-free simulator.
#define CH 128
#define NP (CH + 3)    // 131 layer-1 values (halo)
#define NX (CH + 6)    // 134 x-sincos values

// per-axis Lagrange-trig dual basis from (cos a, sin a)
__device__ __forceinline__ void lag3(float cv, float sv, float* e) {
    e[0] = 0.5f * (1.f + cv - sv);
    e[1] = sv;
    e[2] = 0.5f * (1.f - cv - sv);
}

__global__ void __launch_bounds__(256, 1) mega_kernel(const float* __restrict__ x,
                                                      const float* __restrict__ weights,
                                                      const float* __restrict__ dw,
                                                      const float* __restrict__ db,
                                                      float* __restrict__ out) {
    __shared__ float cw[24], sw[24];     // producer warp only
    __shared__ float coef[648];          // [ch][81] raw grid values
    __shared__ float xc[NX], xs[NX];     // sincos of input window
    __shared__ float ac[NP], as_[NP];    // sincos of layer-1 relu values
    __shared__ float red[8];

    int t = threadIdx.x;
    int lane = t & 31;
    int wid = t >> 5;
    int bid = blockIdx.x;                // 0..255
    int b  = bid >> 3;                   // batch 0..31
    int s0 = (bid & 7) * CH;             // chunk start

    // ---- x-window sincos (threads 64..197): independent of producers ----
    {
        int k = t - 64;
        if (k >= 0 && k < NX) {
            int l = s0 - 2 + k;
            float cv = 1.f, sv = 0.f;
            if (l >= 0 && l < 1024) __sincosf(x[b * 1024 + l], &sv, &cv);
            xc[k] = cv; xs[k] = sv;
        }
    }

    // ---- producer: blocks 0..80, warp 0 simulates grid circuit n = bid ----
    if (bid < 81 && wid == 0) {
        if (lane < 24) {
            const float TWO_PI = 6.28318530717958647692f;
            float w = weights[lane];
            float wm = fmodf(w, TWO_PI);
            if (wm < 0.f) wm += TWO_PI;
            float sv, cv;
            __sincosf(0.5f * wm, &sv, &cv);
            cw[lane] = cv;
            sw[lane] = sv;
        }
        __syncwarp();

        St st;
#pragma unroll
        for (int m = 0; m < 8; ++m) st.a[m] = make_float2(0.f, 0.f);
        if (lane == 0) st.a[0] = make_float2(1.f, 0.f);
        ansatz(st, &cw[0], &sw[0], lane);

        const float GC[3] = {1.f, 0.70710678118654752440f, 0.f};
        const float GS[3] = {0.f, 0.70710678118654752440f, 1.f};
        int n = bid;
        int k0 = n / 27, k1 = (n / 9) % 3, k2 = (n / 3) % 3, k3 = n % 3;
        gateRY<0>(st, GC[k0], GS[k0], lane);
        gateRY<1>(st, GC[k1], GS[k1], lane);
        gateRY<2>(st, GC[k2], GS[k2], lane);
        gateRY<3>(st, GC[k3], GS[k3], lane);

        ansatz(st, &cw[8],  &sw[8],  lane);
        ansatz(st, &cw[16], &sw[16], lane);

        float vj[8];
#pragma unroll
        for (int j = 0; j < 8; ++j) vj[j] = 0.f;
#pragma unroll
        for (int m = 0; m < 8; ++m) {
            float2 a = st.a[m];
            float p = a.x * a.x + a.y * a.y;
            int idx = (lane << 3) | m;
#pragma unroll
            for (int j = 0; j < 8; ++j) vj[j] += ((idx >> (7 - j)) & 1) ? -p : p;
        }
#pragma unroll
        for (int j = 0; j < 8; ++j) {
#pragma unroll
            for (int o = 16; o; o >>= 1) vj[j] += __shfl_xor_sync(FULL, vj[j], o);
        }
        if (lane == 0) {
#pragma unroll
            for (int j = 0; j < 8; ++j) g_F[j * 81 + n] = vj[j];
            __threadfence();                 // publish g_F before counting
            atomicAdd(&g_ctr, 1u);
        }
    }

    // ---- flag-sync: volatile poll (no atomic storm), one thread/block ----
    if (t == 0) {
        volatile unsigned* pc = &g_ctr;
        while (*pc < 81u) __nanosleep(256);
        __threadfence();                     // acquire: order g_F reads after
    }
    __syncthreads();

    // ---- copy raw grid values (dual basis: no transform needed) ----
    for (int i = t; i < 648; i += 256) coef[i] = g_F[i];
    __syncthreads();

    // ---- layer 1: thread-per-position (p = s0 - 1 + t), t < NP ----
    if (t < NP) {
        int p = s0 - 1 + t;
        float cv = 1.f, sv = 0.f;            // OOB position -> angle 0
        if (p >= 0 && p < 1023) {
            float e0[3], e1[3], t23[9];
            lag3(xc[t], xs[t], e0);
            lag3(xc[t + 1], xs[t + 1], e1);
            {
                float e2[3], e3[3];
                lag3(xc[t + 2], xs[t + 2], e2);
                lag3(xc[t + 3], xs[t + 3], e3);
#pragma unroll
                for (int i = 0; i < 3; ++i)
#pragma unroll
                    for (int j = 0; j < 3; ++j) t23[i * 3 + j] = e2[i] * e3[j];
            }
            float v = 0.f;
#pragma unroll
            for (int i = 0; i < 9; ++i) {
                float pp = 0.f;
#pragma unroll
                for (int l = 0; l < 9; ++l) pp = fmaf(coef[i * 9 + l], t23[l], pp);
                v = fmaf(e0[i / 3] * e1[i % 3], pp, v);
            }
            __sincosf(fmaxf(v, 0.f), &sv, &cv);
        }
        ac[t] = cv; as_[t] = sv;
    }
    __syncthreads();

    // ---- layer 2: thread = (channel = t&7, 4 positions 4q..4q+3) ----
    int ch = t & 7;
    int q  = t >> 3;
    int p0 = 4 * q;

    float t23[4][9];
    float e0r[4][3], e1r[4][3];
#pragma unroll
    for (int r = 0; r < 4; ++r) {
        int p = p0 + r;
        lag3(ac[p],     as_[p],     e0r[r]);
        lag3(ac[p + 1], as_[p + 1], e1r[r]);
        float e2[3], e3[3];
        lag3(ac[p + 2], as_[p + 2], e2);
        lag3(ac[p + 3], as_[p + 3], e3);
#pragma unroll
        for (int i = 0; i < 3; ++i)
#pragma unroll
            for (int j = 0; j < 3; ++j) t23[r][i * 3 + j] = e2[i] * e3[j];
    }

    const float* sc = &coef[ch * 81];
    float acc[4] = {0.f, 0.f, 0.f, 0.f};
#pragma unroll
    for (int i = 0; i < 9; ++i) {
        float row[9];
#pragma unroll
        for (int l = 0; l < 9; ++l) row[l] = sc[i * 9 + l];
#pragma unroll
        for (int r = 0; r < 4; ++r) {
            float d = 0.f;
#pragma unroll
            for (int l = 0; l < 9; ++l) d = fmaf(row[l], t23[r][l], d);
            acc[r] = fmaf(e0r[r][i / 3] * e1r[r][i % 3], d, acc[r]);
        }
    }

    // channel max across octet (warp-uniform shuffles)
#pragma unroll
    for (int r = 0; r < 4; ++r) {
        acc[r] = fmaxf(acc[r], __shfl_xor_sync(FULL, acc[r], 1));
        acc[r] = fmaxf(acc[r], __shfl_xor_sync(FULL, acc[r], 2));
        acc[r] = fmaxf(acc[r], __shfl_xor_sync(FULL, acc[r], 4));
    }

    // dense contributions (relu(max) == max(relu))
    float contrib = 0.f;
    if (ch == 0) {
#pragma unroll
        for (int r = 0; r < 4; ++r) {
            int s = s0 + p0 + r;
            if (s < 1022) contrib += fmaxf(acc[r], 0.f) * dw[s];
        }
    }
    contrib += __shfl_xor_sync(FULL, contrib, 8);
    contrib += __shfl_xor_sync(FULL, contrib, 16);
    if (lane == 0) red[wid] = contrib;
    __syncthreads();

    // ---- block total -> global partial; last block finalizes + resets ----
    if (t == 0) {
        float r = 0.f;
#pragma unroll
        for (int w = 0; w < 8; ++w) r += red[w];
        atomicAdd(&g_partial[b], r);
        __threadfence();                        // partial visible before done++
        unsigned old = atomicAdd(&g_done, 1u);
        if (old == 255u) {                      // last block of this replay
            __threadfence();
            float bias = db[0];
#pragma unroll 4
            for (int bb = 0; bb < 32; ++bb) {
                float p = atomicAdd(&g_partial[bb], 0.f);   // coherent read
                out[bb] = p + bias;
                atomicExch(&g_partial[bb], 0.f);            // reset for next replay
            }
            atomicExch(&g_ctr, 0u);
            atomicExch(&g_done, 0u);
            __threadfence();
        }
    }
}

// ---------------- launch ------------------------------------------------------
extern "C" void kernel_launch(void* const* d_in, const int* in_sizes, int n_in,
                              void* d_out, int out_size) {
    const float* x       = (const float*)d_in[0];   // (32,1024,1)
    const float* weights = (const float*)d_in[1];   // (3,8)
    const float* dw      = (const float*)d_in[2];   // (1022,1)
    const float* db      = (const float*)d_in[3];   // (1,)
    float* out = (float*)d_out;                     // (32,1)

    mega_kernel<<<256, 256>>>(x, weights, dw, db, out);
}

// round 13
// speedup vs baseline: 1.7184x; 1.7184x over previous
#include <cuda_runtime.h>

#define FULL 0xffffffffu

// ---------------- scratch ----------------------------------------------------
__device__ float g_F[8 * 81];     // grid evaluations of <Z_j>, layout [j][n]

// ---------------- packed f32x2 helpers (Blackwell) ---------------------------
typedef unsigned long long u64;
__device__ __forceinline__ u64 pk2(float a, float b) {
    u64 r; asm("mov.b64 %0, {%1,%2};" : "=l"(r) : "f"(a), "f"(b)); return r;
}
__device__ __forceinline__ void upk2(u64 v, float& a, float& b) {
    asm("mov.b64 {%0,%1}, %2;" : "=f"(a), "=f"(b) : "l"(v));
}
__device__ __forceinline__ u64 fma2(u64 a, u64 b, u64 c) {
    u64 d; asm("fma.rn.f32x2 %0, %1, %2, %3;" : "=l"(d) : "l"(a), "l"(b), "l"(c)); return d;
}
__device__ __forceinline__ u64 add2(u64 a, u64 b) {
    u64 d; asm("add.rn.f32x2 %0, %1, %2;" : "=l"(d) : "l"(a), "l"(b)); return d;
}

// ---------------- warp statevector simulation (gridsim only) ----------------
struct St { float2 a[8]; };

__device__ __forceinline__ float2 shxor(float2 v, int m) {
    float2 r;
    r.x = __shfl_xor_sync(FULL, v.x, m);
    r.y = __shfl_xor_sync(FULL, v.y, m);
    return r;
}

template<int Q>
__device__ __forceinline__ void gateRY(St& st, float c, float s, int lane) {
    constexpr int lm = 1 << (4 - Q);
    float sg = (lane & lm) ? s : -s;
#pragma unroll
    for (int m = 0; m < 8; ++m) {
        float2 o = shxor(st.a[m], lm);
        float2 a = st.a[m];
        st.a[m] = make_float2(c * a.x + sg * o.x, c * a.y + sg * o.y);
    }
}

template<int Q>
__device__ __forceinline__ void gateRX(St& st, float c, float s, int lane) {
    if constexpr (Q >= 5) {
        constexpr int bit = 1 << (7 - Q);
#pragma unroll
        for (int m = 0; m < 8; ++m) {
            if ((m & bit) == 0) {
                float2 a = st.a[m], b = st.a[m | bit];
                st.a[m]       = make_float2(c * a.x + s * b.y, c * a.y - s * b.x);
                st.a[m | bit] = make_float2(c * b.x + s * a.y, c * b.y - s * a.x);
            }
        }
    } else {
        constexpr int lm = 1 << (4 - Q);
#pragma unroll
        for (int m = 0; m < 8; ++m) {
            float2 o = shxor(st.a[m], lm);
            float2 a = st.a[m];
            st.a[m] = make_float2(c * a.x + s * o.y, c * a.y - s * o.x);
        }
    }
}

template<int Q>
__device__ __forceinline__ void gateRZ(St& st, float c, float s, int lane) {
    if constexpr (Q >= 5) {
        constexpr int bit = 1 << (7 - Q);
#pragma unroll
        for (int m = 0; m < 8; ++m) {
            float f = (m & bit) ? s : -s;
            float2 a = st.a[m];
            st.a[m] = make_float2(c * a.x - f * a.y, c * a.y + f * a.x);
        }
    } else {
        constexpr int lm = 1 << (4 - Q);
        float f = (lane & lm) ? s : -s;
#pragma unroll
        for (int m = 0; m < 8; ++m) {
            float2 a = st.a[m];
            st.a[m] = make_float2(c * a.x - f * a.y, c * a.y + f * a.x);
        }
    }
}

// Fused CNOT·RY·CNOT (round-10 derivation)
template<int J>
__device__ __forceinline__ void fusedW(St& st, float c, float s, int lane) {
    if constexpr (J <= 3) {
        constexpr int cm = 1 << (4 - J);
        constexpr int tm = 1 << (3 - J);
        float sg = (lane & cm) ? s : -s;
#pragma unroll
        for (int m = 0; m < 8; ++m) {
            float2 o = shxor(st.a[m], cm | tm);
            float2 a = st.a[m];
            st.a[m] = make_float2(c * a.x + sg * o.x, c * a.y + sg * o.y);
        }
    } else if constexpr (J == 4) {
        float sg = (lane & 1) ? s : -s;
        float2 o[8];
#pragma unroll
        for (int m = 0; m < 8; ++m) o[m] = shxor(st.a[m ^ 4], 1);
#pragma unroll
        for (int m = 0; m < 8; ++m) {
            float2 a = st.a[m];
            st.a[m] = make_float2(c * a.x + sg * o[m].x, c * a.y + sg * o[m].y);
        }
    } else if constexpr (J == 5 || J == 6) {
        constexpr int cmask = (J == 5) ? 4 : 2;
        constexpr int xmask = (J == 5) ? 6 : 3;
        float2 old[8];
#pragma unroll
        for (int m = 0; m < 8; ++m) old[m] = st.a[m];
#pragma unroll
        for (int m = 0; m < 8; ++m) {
            float sg = (m & cmask) ? s : -s;
            st.a[m] = make_float2(c * old[m].x + sg * old[m ^ xmask].x,
                                  c * old[m].y + sg * old[m ^ xmask].y);
        }
    } else {
        int bc = (lane >> 4) & 1;
        float2 old[8];
#pragma unroll
        for (int m = 0; m < 8; ++m) old[m] = st.a[m];
#pragma unroll
        for (int m = 0; m < 8; ++m) {
            float sg = ((bc ^ (m & 1)) != 0) ? s : -s;
            st.a[m] = make_float2(c * old[m].x + sg * old[m ^ 1].x,
                                  c * old[m].y + sg * old[m ^ 1].y);
        }
    }
}

template<int J>
__device__ __forceinline__ void ansatzStep(St& st, const float* cw, const float* sw, int lane) {
    float c = cw[J], s = sw[J];
    gateRX<J>(st, c, s, lane);
    fusedW<J>(st, c, s, lane);
    gateRZ<J>(st, c, s, lane);
}

__device__ __forceinline__ void ansatz(St& st, const float* cw, const float* sw, int lane) {
    ansatzStep<0>(st, cw, sw, lane);
    ansatzStep<1>(st, cw, sw, lane);
    ansatzStep<2>(st, cw, sw, lane);
    ansatzStep<3>(st, cw, sw, lane);
    ansatzStep<4>(st, cw, sw, lane);
    ansatzStep<5>(st, cw, sw, lane);
    ansatzStep<6>(st, cw, sw, lane);
    ansatzStep<7>(st, cw, sw, lane);
}

// ---------------- kernel 1: 81 grid circuits ---------------------------------
__global__ void gridsim_kernel(const float* __restrict__ weights,
                               const float* __restrict__ db,
                               float* __restrict__ out) {
    __shared__ float cw[24], sw[24];
    int lane = threadIdx.x;

    if (blockIdx.x == 0) out[lane] = db[0];   // seed output with bias

    if (lane < 24) {
        const float TWO_PI = 6.28318530717958647692f;
        float w = weights[lane];
        float wm = fmodf(w, TWO_PI);
        if (wm < 0.f) wm += TWO_PI;
        float sv, cv;
        __sincosf(0.5f * wm, &sv, &cv);
        cw[lane] = cv;
        sw[lane] = sv;
    }
    __syncwarp();

    St st;
#pragma unroll
    for (int m = 0; m < 8; ++m) st.a[m] = make_float2(0.f, 0.f);
    if (lane == 0) st.a[0] = make_float2(1.f, 0.f);
    ansatz(st, &cw[0], &sw[0], lane);

    const float GC[3] = {1.f, 0.70710678118654752440f, 0.f};
    const float GS[3] = {0.f, 0.70710678118654752440f, 1.f};
    int n = blockIdx.x;
    int k0 = n / 27, k1 = (n / 9) % 3, k2 = (n / 3) % 3, k3 = n % 3;
    gateRY<0>(st, GC[k0], GS[k0], lane);
    gateRY<1>(st, GC[k1], GS[k1], lane);
    gateRY<2>(st, GC[k2], GS[k2], lane);
    gateRY<3>(st, GC[k3], GS[k3], lane);

    ansatz(st, &cw[8],  &sw[8],  lane);
    ansatz(st, &cw[16], &sw[16], lane);

    float vj[8];
#pragma unroll
    for (int j = 0; j < 8; ++j) vj[j] = 0.f;
#pragma unroll
    for (int m = 0; m < 8; ++m) {
        float2 a = st.a[m];
        float p = a.x * a.x + a.y * a.y;
        int idx = (lane << 3) | m;
#pragma unroll
        for (int j = 0; j < 8; ++j) vj[j] += ((idx >> (7 - j)) & 1) ? -p : p;
    }
#pragma unroll
    for (int j = 0; j < 8; ++j) {
#pragma unroll
        for (int o = 16; o; o >>= 1) vj[j] += __shfl_xor_sync(FULL, vj[j], o);
    }
    if (lane == 0) {
#pragma unroll
        for (int j = 0; j < 8; ++j) g_F[j * 81 + n] = vj[j];
    }
}

// ---------------- kernel 2: layer1 + layer2 + pool + dense -------------------
// CH=64 -> 512 blocks. thread = (channel = t&7, packed position pair 2q/2q+1).
// Coefficients duplicated in smem as float2{v,v} so one LDS.64 feeds FFMA2.
#define CH 64
#define NP (CH + 3)    // 67 layer-1 values (halo)
#define NX (CH + 6)    // 70 x-sincos values

// per-axis Lagrange-trig dual basis from (cos a, sin a)
__device__ __forceinline__ void lag3(float cv, float sv, float* e) {
    e[0] = 0.5f * (1.f + cv - sv);
    e[1] = sv;
    e[2] = 0.5f * (1.f - cv - sv);
}

__global__ void __launch_bounds__(256) fused_kernel(const float* __restrict__ x,
                                                    const float* __restrict__ dw,
                                                    float* __restrict__ out) {
    __shared__ float2 coefd[648];        // [ch][81], both halves = value
    __shared__ float  coef0[81];         // channel 0 scalar copy (layer 1)
    __shared__ float  xc[NX], xs[NX];    // sincos of input window
    __shared__ float  ac[NP], as_[NP];   // sincos of layer-1 relu values
    __shared__ float  red[8];

    int t = threadIdx.x;
    int lane = t & 31;
    int warp = t >> 5;
    int b = blockIdx.y;
    int s0 = blockIdx.x * CH;

    // --- load grid values: duplicate-pair copy + scalar ch0 copy ---
    for (int i = t; i < 648; i += 256) {
        float v = g_F[i];
        coefd[i] = make_float2(v, v);
    }
    if (t >= 128 && t < 209) coef0[t - 128] = g_F[t - 128];
    // --- sincos of x window: x index l = s0-2+k ---
    if (t < NX) {
        int l = s0 - 2 + t;
        float cv = 1.f, sv = 0.f;
        if (l >= 0 && l < 1024) __sincosf(x[b * 1024 + l], &sv, &cv);
        xc[t] = cv; xs[t] = sv;
    }
    __syncthreads();

    // --- layer 1: thread-per-position (p = s0 - 1 + t), t < NP=67 ---
    if (t < NP) {
        int p = s0 - 1 + t;
        float cv = 1.f, sv = 0.f;          // OOB position -> angle 0
        if (p >= 0 && p < 1023) {
            float e0[3], e1[3], t23[9];
            lag3(xc[t], xs[t], e0);
            lag3(xc[t + 1], xs[t + 1], e1);
            {
                float e2[3], e3[3];
                lag3(xc[t + 2], xs[t + 2], e2);
                lag3(xc[t + 3], xs[t + 3], e3);
#pragma unroll
                for (int i = 0; i < 3; ++i)
#pragma unroll
                    for (int j = 0; j < 3; ++j) t23[i * 3 + j] = e2[i] * e3[j];
            }
            float v = 0.f;
#pragma unroll
            for (int i = 0; i < 9; ++i) {
                float pp = 0.f;
#pragma unroll
                for (int l = 0; l < 9; ++l) pp = fmaf(coef0[i * 9 + l], t23[l], pp);
                v = fmaf(e0[i / 3] * e1[i % 3], pp, v);
            }
            __sincosf(fmaxf(v, 0.f), &sv, &cv);
        }
        ac[t] = cv; as_[t] = sv;
    }
    __syncthreads();

    // --- layer 2: packed pair of positions per thread ---
    int ch = t & 7;
    int q  = t >> 3;                     // 0..31 -> local positions 2q, 2q+1
    int pA = 2 * q, pB = 2 * q + 1;

    // dual-basis factors for both positions
    float e0a[3], e1a[3], e0b[3], e1b[3];
    lag3(ac[pA],     as_[pA],     e0a);
    lag3(ac[pA + 1], as_[pA + 1], e1a);
    lag3(ac[pB],     as_[pB],     e0b);
    lag3(ac[pB + 1], as_[pB + 1], e1b);

    // packed t23 tensor: lane0 = position A, lane1 = position B
    u64 t23p[9];
    {
        float e2a[3], e3a[3], e2b[3], e3b[3];
        lag3(ac[pA + 2], as_[pA + 2], e2a);
        lag3(ac[pA + 3], as_[pA + 3], e3a);
        lag3(ac[pB + 2], as_[pB + 2], e2b);
        lag3(ac[pB + 3], as_[pB + 3], e3b);
#pragma unroll
        for (int i = 0; i < 3; ++i)
#pragma unroll
            for (int j = 0; j < 3; ++j)
                t23p[i * 3 + j] = pk2(e2a[i] * e3a[j], e2b[i] * e3b[j]);
    }

    const u64* scp = reinterpret_cast<const u64*>(&coefd[ch * 81]);
    u64 acc2 = 0;                         // packed (accA, accB)
#pragma unroll
    for (int i = 0; i < 9; ++i) {
        u64 dEven = 0, dOdd = 0;          // ILP-2 split of the 9-dot
#pragma unroll
        for (int l = 0; l < 9; l += 2) dEven = fma2(scp[i * 9 + l], t23p[l], dEven);
#pragma unroll
        for (int l = 1; l < 9; l += 2) dOdd  = fma2(scp[i * 9 + l], t23p[l], dOdd);
        u64 d2 = add2(dEven, dOdd);
        u64 e2p = pk2(e0a[i / 3] * e1a[i % 3], e0b[i / 3] * e1b[i % 3]);
        acc2 = fma2(e2p, d2, acc2);
    }
    float acc0, acc1;
    upk2(acc2, acc0, acc1);

    // channel max across octet (warp-uniform shuffles)
    acc0 = fmaxf(acc0, __shfl_xor_sync(FULL, acc0, 1));
    acc0 = fmaxf(acc0, __shfl_xor_sync(FULL, acc0, 2));
    acc0 = fmaxf(acc0, __shfl_xor_sync(FULL, acc0, 4));
    acc1 = fmaxf(acc1, __shfl_xor_sync(FULL, acc1, 1));
    acc1 = fmaxf(acc1, __shfl_xor_sync(FULL, acc1, 2));
    acc1 = fmaxf(acc1, __shfl_xor_sync(FULL, acc1, 4));

    // dense contributions (relu(max) == max(relu))
    float contrib = 0.f;
    if (ch == 0) {
        int sA = s0 + pA, sB = s0 + pB;
        if (sA < 1022) contrib += fmaxf(acc0, 0.f) * dw[sA];
        if (sB < 1022) contrib += fmaxf(acc1, 0.f) * dw[sB];
    }
    contrib += __shfl_xor_sync(FULL, contrib, 8);
    contrib += __shfl_xor_sync(FULL, contrib, 16);
    if (lane == 0) red[warp] = contrib;
    __syncthreads();
    if (warp == 0) {
        float r = (lane < 8) ? red[lane] : 0.f;
        r += __shfl_xor_sync(FULL, r, 1);
        r += __shfl_xor_sync(FULL, r, 2);
        r += __shfl_xor_sync(FULL, r, 4);
        if (lane == 0) atomicAdd(&out[b], r);
    }
}

// ---------------- launch ------------------------------------------------------
extern "C" void kernel_launch(void* const* d_in, const int* in_sizes, int n_in,
                              void* d_out, int out_size) {
    const float* x       = (const float*)d_in[0];   // (32,1024,1)
    const float* weights = (const float*)d_in[1];   // (3,8)
    const float* dw      = (const float*)d_in[2];   // (1022,1)
    const float* db      = (const float*)d_in[3];   // (1,)
    float* out = (float*)d_out;                     // (32,1)

    gridsim_kernel<<<81, 32>>>(weights, db, out);
    dim3 g((1022 + CH - 1) / CH, 32);               // (16, 32)
    fused_kernel<<<g, 256>>>(x, dw, out);
}

// round 14
// speedup vs baseline: 1.9801x; 1.1523x over previous
#include <cuda_runtime.h>

#define FULL 0xffffffffu

// ---------------- scratch ----------------------------------------------------
__device__ float g_F[8 * 81];     // grid evaluations of <Z_j>, layout [j][n]

// ---------------- warp statevector simulation (gridsim only) ----------------
// flat index i = lane*8 + m. qubit q (0..4) -> lane bit (4-q); qubit q (5..7)
// -> m bit (7-q).
struct St { float2 a[8]; };

__device__ __forceinline__ float2 shxor(float2 v, int m) {
    float2 r;
    r.x = __shfl_xor_sync(FULL, v.x, m);
    r.y = __shfl_xor_sync(FULL, v.y, m);
    return r;
}

// RY (data encoding on qubits 0-3: lane-bit qubits)
template<int Q>
__device__ __forceinline__ void gateRY(St& st, float c, float s, int lane) {
    constexpr int lm = 1 << (4 - Q);
    float sg = (lane & lm) ? s : -s;
#pragma unroll
    for (int m = 0; m < 8; ++m) {
        float2 o = shxor(st.a[m], lm);
        float2 a = st.a[m];
        st.a[m] = make_float2(c * a.x + sg * o.x, c * a.y + sg * o.y);
    }
}

// RX = [[c,-is],[-is,c]]
template<int Q>
__device__ __forceinline__ void gateRX(St& st, float c, float s, int lane) {
    if constexpr (Q >= 5) {
        constexpr int bit = 1 << (7 - Q);
#pragma unroll
        for (int m = 0; m < 8; ++m) {
            if ((m & bit) == 0) {
                float2 a = st.a[m], b = st.a[m | bit];
                st.a[m]       = make_float2(c * a.x + s * b.y, c * a.y - s * b.x);
                st.a[m | bit] = make_float2(c * b.x + s * a.y, c * b.y - s * a.x);
            }
        }
    } else {
        constexpr int lm = 1 << (4 - Q);
#pragma unroll
        for (int m = 0; m < 8; ++m) {
            float2 o = shxor(st.a[m], lm);
            float2 a = st.a[m];
            st.a[m] = make_float2(c * a.x + s * o.y, c * a.y - s * o.x);
        }
    }
}

// RZ = diag(e^{-it/2}, e^{+it/2})
template<int Q>
__device__ __forceinline__ void gateRZ(St& st, float c, float s, int lane) {
    if constexpr (Q >= 5) {
        constexpr int bit = 1 << (7 - Q);
#pragma unroll
        for (int m = 0; m < 8; ++m) {
            float f = (m & bit) ? s : -s;
            float2 a = st.a[m];
            st.a[m] = make_float2(c * a.x - f * a.y, c * a.y + f * a.x);
        }
    } else {
        constexpr int lm = 1 << (4 - Q);
        float f = (lane & lm) ? s : -s;
#pragma unroll
        for (int m = 0; m < 8; ++m) {
            float2 a = st.a[m];
            st.a[m] = make_float2(c * a.x - f * a.y, c * a.y + f * a.x);
        }
    }
}

// Fused CNOT·RY·CNOT (round-10 derivation)
template<int J>
__device__ __forceinline__ void fusedW(St& st, float c, float s, int lane) {
    if constexpr (J <= 3) {
        constexpr int cm = 1 << (4 - J);
        constexpr int tm = 1 << (3 - J);
        float sg = (lane & cm) ? s : -s;
#pragma unroll
        for (int m = 0; m < 8; ++m) {
            float2 o = shxor(st.a[m], cm | tm);
            float2 a = st.a[m];
            st.a[m] = make_float2(c * a.x + sg * o.x, c * a.y + sg * o.y);
        }
    } else if constexpr (J == 4) {
        float sg = (lane & 1) ? s : -s;
        float2 o[8];
#pragma unroll
        for (int m = 0; m < 8; ++m) o[m] = shxor(st.a[m ^ 4], 1);
#pragma unroll
        for (int m = 0; m < 8; ++m) {
            float2 a = st.a[m];
            st.a[m] = make_float2(c * a.x + sg * o[m].x, c * a.y + sg * o[m].y);
        }
    } else if constexpr (J == 5 || J == 6) {
        constexpr int cmask = (J == 5) ? 4 : 2;
        constexpr int xmask = (J == 5) ? 6 : 3;
        float2 old[8];
#pragma unroll
        for (int m = 0; m < 8; ++m) old[m] = st.a[m];
#pragma unroll
        for (int m = 0; m < 8; ++m) {
            float sg = (m & cmask) ? s : -s;
            st.a[m] = make_float2(c * old[m].x + sg * old[m ^ xmask].x,
                                  c * old[m].y + sg * old[m ^ xmask].y);
        }
    } else {
        int bc = (lane >> 4) & 1;
        float2 old[8];
#pragma unroll
        for (int m = 0; m < 8; ++m) old[m] = st.a[m];
#pragma unroll
        for (int m = 0; m < 8; ++m) {
            float sg = ((bc ^ (m & 1)) != 0) ? s : -s;
            st.a[m] = make_float2(c * old[m].x + sg * old[m ^ 1].x,
                                  c * old[m].y + sg * old[m ^ 1].y);
        }
    }
}

template<int J>
__device__ __forceinline__ void ansatzStep(St& st, const float* cw, const float* sw, int lane) {
    float c = cw[J], s = sw[J];
    gateRX<J>(st, c, s, lane);
    fusedW<J>(st, c, s, lane);
    gateRZ<J>(st, c, s, lane);
}

__device__ __forceinline__ void ansatz(St& st, const float* cw, const float* sw, int lane) {
    ansatzStep<0>(st, cw, sw, lane);
    ansatzStep<1>(st, cw, sw, lane);
    ansatzStep<2>(st, cw, sw, lane);
    ansatzStep<3>(st, cw, sw, lane);
    ansatzStep<4>(st, cw, sw, lane);
    ansatzStep<5>(st, cw, sw, lane);
    ansatzStep<6>(st, cw, sw, lane);
    ansatzStep<7>(st, cw, sw, lane);
}

// ---------------- kernel 1: 81 grid circuits ---------------------------------
__global__ void gridsim_kernel(const float* __restrict__ weights,
                               const float* __restrict__ db,
                               float* __restrict__ out) {
    __shared__ float cw[24], sw[24];
    int lane = threadIdx.x;

    if (blockIdx.x == 0) out[lane] = db[0];   // seed output with bias

    if (lane < 24) {
        const float TWO_PI = 6.28318530717958647692f;
        float w = weights[lane];
        float wm = fmodf(w, TWO_PI);
        if (wm < 0.f) wm += TWO_PI;
        float sv, cv;
        __sincosf(0.5f * wm, &sv, &cv);
        cw[lane] = cv;
        sw[lane] = sv;
    }
    __syncwarp();

    St st;
#pragma unroll
    for (int m = 0; m < 8; ++m) st.a[m] = make_float2(0.f, 0.f);
    if (lane == 0) st.a[0] = make_float2(1.f, 0.f);
    ansatz(st, &cw[0], &sw[0], lane);

    const float GC[3] = {1.f, 0.70710678118654752440f, 0.f};
    const float GS[3] = {0.f, 0.70710678118654752440f, 1.f};
    int n = blockIdx.x;
    int k0 = n / 27, k1 = (n / 9) % 3, k2 = (n / 3) % 3, k3 = n % 3;
    gateRY<0>(st, GC[k0], GS[k0], lane);
    gateRY<1>(st, GC[k1], GS[k1], lane);
    gateRY<2>(st, GC[k2], GS[k2], lane);
    gateRY<3>(st, GC[k3], GS[k3], lane);

    ansatz(st, &cw[8],  &sw[8],  lane);
    ansatz(st, &cw[16], &sw[16], lane);

    float vj[8];
#pragma unroll
    for (int j = 0; j < 8; ++j) vj[j] = 0.f;
#pragma unroll
    for (int m = 0; m < 8; ++m) {
        float2 a = st.a[m];
        float p = a.x * a.x + a.y * a.y;
        int idx = (lane << 3) | m;
#pragma unroll
        for (int j = 0; j < 8; ++j) vj[j] += ((idx >> (7 - j)) & 1) ? -p : p;
    }
#pragma unroll
    for (int j = 0; j < 8; ++j) {
#pragma unroll
        for (int o = 16; o; o >>= 1) vj[j] += __shfl_xor_sync(FULL, vj[j], o);
    }
    if (lane == 0) {
#pragma unroll
        for (int j = 0; j < 8; ++j) g_F[j * 81 + n] = vj[j];
    }
}

// ---------------- kernel 2: layer1 + layer2 + pool + dense (dual basis) -----
// 512 threads; thread = (channel = t&7, 2 positions 2q/2q+1, q = t>>3: 0..63)
// block covers CH = 128 layer-2 positions; grid (8, 32) -> 4096 warps chip-wide
#define CH 128
#define NP (CH + 3)    // 131 layer-1 values (halo)
#define NX (CH + 6)    // 134 x-sincos values

// per-axis Lagrange-trig dual basis from (cos a, sin a):
// L0=(1+c-s)/2, L1=s, L2=(1-c-s)/2 -> raw grid values are the coefficients
__device__ __forceinline__ void lag3(float cv, float sv, float* e) {
    e[0] = 0.5f * (1.f + cv - sv);
    e[1] = sv;
    e[2] = 0.5f * (1.f - cv - sv);
}

__global__ void __launch_bounds__(512) fused_kernel(const float* __restrict__ x,
                                                    const float* __restrict__ dw,
                                                    float* __restrict__ out) {
    __shared__ float coef[648];          // [ch][81] raw grid values
    __shared__ float xc[NX], xs[NX];     // sincos of input window
    __shared__ float ac[NP], as_[NP];    // sincos of layer-1 relu values
    __shared__ float red[16];

    int t = threadIdx.x;
    int lane = t & 31;
    int warp = t >> 5;
    int b = blockIdx.y;
    int s0 = blockIdx.x * CH;

    // --- straight copy (g_F already [j][81]) ---
    for (int i = t; i < 648; i += 512) coef[i] = g_F[i];
    // --- sincos of x window: x index l = s0-2+k ---
    if (t < NX) {
        int l = s0 - 2 + t;
        float cv = 1.f, sv = 0.f;
        if (l >= 0 && l < 1024) __sincosf(x[b * 1024 + l], &sv, &cv);
        xc[t] = cv; xs[t] = sv;
    }
    __syncthreads();

    // --- layer 1: thread-per-position (p = s0 - 1 + t), t < NP=131 ---
    if (t < NP) {
        int p = s0 - 1 + t;
        float cv = 1.f, sv = 0.f;          // OOB position -> angle 0
        if (p >= 0 && p < 1023) {
            float e0[3], e1[3], t23[9];
            lag3(xc[t], xs[t], e0);
            lag3(xc[t + 1], xs[t + 1], e1);
            {
                float e2[3], e3[3];
                lag3(xc[t + 2], xs[t + 2], e2);
                lag3(xc[t + 3], xs[t + 3], e3);
#pragma unroll
                for (int i = 0; i < 3; ++i)
#pragma unroll
                    for (int j = 0; j < 3; ++j) t23[i * 3 + j] = e2[i] * e3[j];
            }
            float v = 0.f;
#pragma unroll
            for (int i = 0; i < 9; ++i) {
                float pp = 0.f;
#pragma unroll
                for (int l = 0; l < 9; ++l) pp = fmaf(coef[i * 9 + l], t23[l], pp);
                v = fmaf(e0[i / 3] * e1[i % 3], pp, v);
            }
            __sincosf(fmaxf(v, 0.f), &sv, &cv);
        }
        ac[t] = cv; as_[t] = sv;
    }
    __syncthreads();

    // --- layer 2: thread = (channel, 2 positions); coef row LDS feeds 2 chains
    int ch = t & 7;
    int q  = t >> 3;                     // 0..63 -> local positions 2q, 2q+1
    int pA = 2 * q, pB = 2 * q + 1;

    float e0a[3], e1a[3], e0b[3], e1b[3];
    lag3(ac[pA],     as_[pA],     e0a);
    lag3(ac[pA + 1], as_[pA + 1], e1a);
    lag3(ac[pB],     as_[pB],     e0b);
    lag3(ac[pB + 1], as_[pB + 1], e1b);

    float t23a[9], t23b[9];
    {
        float e2[3], e3[3];
        lag3(ac[pA + 2], as_[pA + 2], e2);
        lag3(ac[pA + 3], as_[pA + 3], e3);
#pragma unroll
        for (int i = 0; i < 3; ++i)
#pragma unroll
            for (int j = 0; j < 3; ++j) t23a[i * 3 + j] = e2[i] * e3[j];
        lag3(ac[pB + 2], as_[pB + 2], e2);
        lag3(ac[pB + 3], as_[pB + 3], e3);
#pragma unroll
        for (int i = 0; i < 3; ++i)
#pragma unroll
            for (int j = 0; j < 3; ++j) t23b[i * 3 + j] = e2[i] * e3[j];
    }

    const float* sc = &coef[ch * 81];
    float acc0 = 0.f, acc1 = 0.f;
#pragma unroll
    for (int i = 0; i < 9; ++i) {
        float pa = 0.f, pb = 0.f;
#pragma unroll
        for (int l = 0; l < 9; ++l) {
            float c = sc[i * 9 + l];     // one LDS feeds both positions
            pa = fmaf(c, t23a[l], pa);
            pb = fmaf(c, t23b[l], pb);
        }
        acc0 = fmaf(e0a[i / 3] * e1a[i % 3], pa, acc0);
        acc1 = fmaf(e0b[i / 3] * e1b[i % 3], pb, acc1);
    }

    // channel max across octet (warp-uniform shuffles)
    acc0 = fmaxf(acc0, __shfl_xor_sync(FULL, acc0, 1));
    acc0 = fmaxf(acc0, __shfl_xor_sync(FULL, acc0, 2));
    acc0 = fmaxf(acc0, __shfl_xor_sync(FULL, acc0, 4));
    acc1 = fmaxf(acc1, __shfl_xor_sync(FULL, acc1, 1));
    acc1 = fmaxf(acc1, __shfl_xor_sync(FULL, acc1, 2));
    acc1 = fmaxf(acc1, __shfl_xor_sync(FULL, acc1, 4));

    // dense contributions (relu(max) == max(relu))
    float contrib = 0.f;
    if (ch == 0) {
        int sA = s0 + pA, sB = s0 + pB;
        if (sA < 1022) contrib += fmaxf(acc0, 0.f) * dw[sA];
        if (sB < 1022) contrib += fmaxf(acc1, 0.f) * dw[sB];
    }
    contrib += __shfl_xor_sync(FULL, contrib, 8);
    contrib += __shfl_xor_sync(FULL, contrib, 16);
    if (lane == 0) red[warp] = contrib;
    __syncthreads();
    if (warp == 0) {
        float r = (lane < 16) ? red[lane] : 0.f;
        r += __shfl_xor_sync(FULL, r, 1);
        r += __shfl_xor_sync(FULL, r, 2);
        r += __shfl_xor_sync(FULL, r, 4);
        r += __shfl_xor_sync(FULL, r, 8);
        if (lane == 0) atomicAdd(&out[b], r);
    }
}

// ---------------- launch ------------------------------------------------------
extern "C" void kernel_launch(void* const* d_in, const int* in_sizes, int n_in,
                              void* d_out, int out_size) {
    const float* x       = (const float*)d_in[0];   // (32,1024,1)
    const float* weights = (const float*)d_in[1];   // (3,8)
    const float* dw      = (const float*)d_in[2];   // (1022,1)
    const float* db      = (const float*)d_in[3];   // (1,)
    float* out = (float*)d_out;                     // (32,1)

    gridsim_kernel<<<81, 32>>>(weights, db, out);
    dim3 g((1022 + CH - 1) / CH, 32);               // (8, 32)
    fused_kernel<<<g, 512>>>(x, dw, out);
}